// round 4
// baseline (speedup 1.0000x reference)
#include <cuda_runtime.h>
#include <math.h>
#include <stdint.h>

#define NN 4096
#define MEM 512

// ---------------- scratch (static device globals; no allocation) ----------------
__device__ float g_ifou[NN * 2048];
__device__ float g_c[(NN + 1) * MEM];
__device__ float g_h[(NN + 1) * MEM];
__device__ float g_iou[683 * 1536];
__device__ float g_fw[(NN + 1) * MEM];

__device__ __forceinline__ float sigmoidf_(float x) { return 1.0f / (1.0f + expf(-x)); }

__device__ __forceinline__ int child_id(int p, int k) {
    int c = 4 * p - 12289 + k;
    return c < 0 ? NN : c;
}

// ---------------- tf32 helpers ----------------
__device__ __forceinline__ uint32_t f2tf(float x) {
    uint32_t r;
    asm("cvt.rna.tf32.f32 %0, %1;" : "=r"(r) : "f"(x));
    return r;
}
__device__ __forceinline__ void split1(float x, uint32_t& hi, uint32_t& lo) {
    hi = f2tf(x);
    lo = f2tf(x - __uint_as_float(hi));
}
__device__ __forceinline__ void mma8(float* d, const uint32_t* a, const uint32_t* b) {
    asm volatile(
        "mma.sync.aligned.m16n8k8.row.col.f32.tf32.tf32.f32 "
        "{%0,%1,%2,%3}, {%4,%5,%6,%7}, {%8,%9}, {%0,%1,%2,%3};"
        : "+f"(d[0]), "+f"(d[1]), "+f"(d[2]), "+f"(d[3])
        : "r"(a[0]), "r"(a[1]), "r"(a[2]), "r"(a[3]), "r"(b[0]), "r"(b[1]));
}

// ---------------- smem layout ----------------
// A: [2 buf][2 split][16 k][128 row]  (uint32), B likewise, B at +8192 words.
// XOR-8 swizzle on the row/col index keyed by (k&3) -> conflict-free frag loads.
constexpr int KC = 16;
constexpr int NCH = 512 / KC;  // 32
__device__ __forceinline__ int a_idx(int buf, int split, int k, int row) {
    return ((buf * 2 + split) * KC + k) * 128 + (row ^ ((k & 3) << 3));
}
__device__ __forceinline__ int b_idx(int buf, int split, int k, int col) {
    return 8192 + ((buf * 2 + split) * KC + k) * 128 + (col ^ ((k & 3) << 3));
}
constexpr int SMEM_BYTES = 16384 * 4;  // 64 KB

// ======================= tf32 mma GEMM =======================
// C[M,Ncol] = A[M,512] @ B[512,Ncol] + bias (fp32 via 3xTF32 split)
// MODE 0: dense A.  MODE 1: A row m = sum of 4 child h-rows of node pbase+m.
template <int MODE>
__global__ __launch_bounds__(256, 1)
void gemm_mma(const float* __restrict__ A, const float* __restrict__ B,
              const float* __restrict__ bias, float* __restrict__ C,
              const float* __restrict__ H, int M, int Ncol, int pbase) {
    extern __shared__ uint32_t sm[];
    const int tid = threadIdx.x;
    const int wid = tid >> 5;
    const int lid = tid & 31;
    const int bm = blockIdx.y * 128;
    const int bn = blockIdx.x * 128;
    const int wm = (wid & 1) * 64;
    const int wn = (wid >> 1) * 32;
    const int g = lid >> 2;
    const int c3 = lid & 3;

    // staging assignments
    const int arow = tid >> 1;            // 0..127
    const int akh = (tid & 1) * 8;        // 0 or 8
    const int bk = tid >> 4;              // 0..15
    const int bn0 = (tid & 15) * 8;       // 0..120

    float ra[8], rb[8];

    auto loadAB = [&](int kb) {
        float4 v0 = make_float4(0.f, 0.f, 0.f, 0.f), v1 = v0;
        int gr = bm + arow;
        if (gr < M) {
            if (MODE == 0) {
                v0 = *reinterpret_cast<const float4*>(A + (size_t)gr * 512 + kb + akh);
                v1 = *reinterpret_cast<const float4*>(A + (size_t)gr * 512 + kb + akh + 4);
            } else {
                int p = pbase + gr;
#pragma unroll
                for (int kk = 0; kk < 4; ++kk) {
                    int cid = child_id(p, kk);
                    const float* hp = H + (size_t)cid * 512 + kb + akh;
                    float4 t0 = *reinterpret_cast<const float4*>(hp);
                    float4 t1 = *reinterpret_cast<const float4*>(hp + 4);
                    v0.x += t0.x; v0.y += t0.y; v0.z += t0.z; v0.w += t0.w;
                    v1.x += t1.x; v1.y += t1.y; v1.z += t1.z; v1.w += t1.w;
                }
            }
        }
        ra[0] = v0.x; ra[1] = v0.y; ra[2] = v0.z; ra[3] = v0.w;
        ra[4] = v1.x; ra[5] = v1.y; ra[6] = v1.z; ra[7] = v1.w;
        const float* bp = B + (size_t)(kb + bk) * Ncol + bn + bn0;
        float4 w0 = *reinterpret_cast<const float4*>(bp);
        float4 w1 = *reinterpret_cast<const float4*>(bp + 4);
        rb[0] = w0.x; rb[1] = w0.y; rb[2] = w0.z; rb[3] = w0.w;
        rb[4] = w1.x; rb[5] = w1.y; rb[6] = w1.z; rb[7] = w1.w;
    };

    auto storeAB = [&](int buf) {
#pragma unroll
        for (int i = 0; i < 8; ++i) {
            uint32_t hi, lo;
            split1(ra[i], hi, lo);
            sm[a_idx(buf, 0, akh + i, arow)] = hi;
            sm[a_idx(buf, 1, akh + i, arow)] = lo;
        }
#pragma unroll
        for (int i = 0; i < 8; ++i) {
            uint32_t hi, lo;
            split1(rb[i], hi, lo);
            sm[b_idx(buf, 0, bk, bn0 + i)] = hi;
            sm[b_idx(buf, 1, bk, bn0 + i)] = lo;
        }
    };

    float acc[4][4][4];
#pragma unroll
    for (int mt = 0; mt < 4; ++mt)
#pragma unroll
        for (int nt = 0; nt < 4; ++nt)
#pragma unroll
            for (int i = 0; i < 4; ++i) acc[mt][nt][i] = 0.f;

    auto compute = [&](int buf) {
#pragma unroll
        for (int ks = 0; ks < KC; ks += 8) {
            uint32_t ah[4][4], al[4][4], bh[4][2], bl[4][2];
#pragma unroll
            for (int mt = 0; mt < 4; ++mt) {
                int r0 = wm + mt * 16 + g;
                ah[mt][0] = sm[a_idx(buf, 0, ks + c3, r0)];
                ah[mt][1] = sm[a_idx(buf, 0, ks + c3, r0 + 8)];
                ah[mt][2] = sm[a_idx(buf, 0, ks + c3 + 4, r0)];
                ah[mt][3] = sm[a_idx(buf, 0, ks + c3 + 4, r0 + 8)];
                al[mt][0] = sm[a_idx(buf, 1, ks + c3, r0)];
                al[mt][1] = sm[a_idx(buf, 1, ks + c3, r0 + 8)];
                al[mt][2] = sm[a_idx(buf, 1, ks + c3 + 4, r0)];
                al[mt][3] = sm[a_idx(buf, 1, ks + c3 + 4, r0 + 8)];
            }
#pragma unroll
            for (int nt = 0; nt < 4; ++nt) {
                int n0 = wn + nt * 8 + g;
                bh[nt][0] = sm[b_idx(buf, 0, ks + c3, n0)];
                bh[nt][1] = sm[b_idx(buf, 0, ks + c3 + 4, n0)];
                bl[nt][0] = sm[b_idx(buf, 1, ks + c3, n0)];
                bl[nt][1] = sm[b_idx(buf, 1, ks + c3 + 4, n0)];
            }
#pragma unroll
            for (int mt = 0; mt < 4; ++mt)
#pragma unroll
                for (int nt = 0; nt < 4; ++nt) {
                    mma8(acc[mt][nt], ah[mt], bh[nt]);
                    mma8(acc[mt][nt], ah[mt], bl[nt]);
                    mma8(acc[mt][nt], al[mt], bh[nt]);
                }
        }
    };

    // pipeline
    loadAB(0);
    storeAB(0);
    __syncthreads();
    for (int ch = 0; ch < NCH; ++ch) {
        if (ch + 1 < NCH) loadAB((ch + 1) * KC);
        compute(ch & 1);
        __syncthreads();
        if (ch + 1 < NCH) {
            storeAB((ch + 1) & 1);
            __syncthreads();
        }
    }

    // epilogue
#pragma unroll
    for (int mt = 0; mt < 4; ++mt) {
        int r = bm + wm + mt * 16 + g;
        int r2 = r + 8;
#pragma unroll
        for (int nt = 0; nt < 4; ++nt) {
            int col = bn + wn + nt * 8 + 2 * c3;
            float b0 = bias[col], b1 = bias[col + 1];
            if (r < M) {
                float2 o = make_float2(acc[mt][nt][0] + b0, acc[mt][nt][1] + b1);
                *reinterpret_cast<float2*>(&C[(size_t)r * Ncol + col]) = o;
            }
            if (r2 < M) {
                float2 o = make_float2(acc[mt][nt][2] + b0, acc[mt][nt][3] + b1);
                *reinterpret_cast<float2*>(&C[(size_t)r2 * Ncol + col]) = o;
            }
        }
    }
}

// ---------------- elementwise kernels ----------------
__global__ void init_kernel(float* cbuf, float* hbuf, float* fw) {
    int j = threadIdx.x;
    cbuf[(size_t)NN * MEM + j] = 0.f;
    hbuf[(size_t)NN * MEM + j] = 0.f;
    fw[(size_t)NN * MEM + j] = 0.f;
}

__global__ void leaf_kernel(const float* __restrict__ ifou, const float* __restrict__ bs,
                            float* __restrict__ cbuf, float* __restrict__ hbuf) {
    int p = blockIdx.x;
    int j = threadIdx.x;
    const float* r = ifou + (size_t)p * 2048;
    float iv = sigmoidf_(r[j] + bs[j]);
    float ov = sigmoidf_(r[1024 + j] + bs[512 + j]);
    float uv = tanhf(r[1536 + j] + bs[1024 + j]);
    float c = iv * uv;
    cbuf[(size_t)p * MEM + j] = c;
    hbuf[(size_t)p * MEM + j] = ov * tanhf(c);
}

__global__ void combine_kernel(const float* __restrict__ ifou, const float* __restrict__ iou,
                               const float* __restrict__ fw, float* __restrict__ cbuf,
                               float* __restrict__ hbuf, int base) {
    int m = blockIdx.x;
    int j = threadIdx.x;
    int p = base + m;
    const float* r = ifou + (size_t)p * 2048;
    float ix = r[j], fx = r[512 + j], ox = r[1024 + j], ux = r[1536 + j];
    float iv = sigmoidf_(ix + iou[(size_t)m * 1536 + j]);
    float ov = sigmoidf_(ox + iou[(size_t)m * 1536 + 512 + j]);
    float uv = tanhf(ux + iou[(size_t)m * 1536 + 1024 + j]);
    float c = iv * uv;
#pragma unroll
    for (int k = 0; k < 4; ++k) {
        int cid = child_id(p, k);
        float f = sigmoidf_(fw[(size_t)cid * MEM + j] + fx);
        c += f * cbuf[(size_t)cid * MEM + j];
    }
    cbuf[(size_t)p * MEM + j] = c;
    hbuf[(size_t)p * MEM + j] = ov * tanhf(c);
}

__global__ void copyout_kernel(const float* __restrict__ hbuf, float* __restrict__ out) {
    out[threadIdx.x] = hbuf[(size_t)(NN - 1) * MEM + threadIdx.x];
}

// ---------------- launch ----------------
extern "C" void kernel_launch(void* const* d_in, const int* in_sizes, int n_in,
                              void* d_out, int out_size) {
    const float* inputs = (const float*)d_in[0];
    const float* Wx     = (const float*)d_in[1];
    const float* bx     = (const float*)d_in[2];
    const float* Ws     = (const float*)d_in[3];
    const float* bs     = (const float*)d_in[4];
    const float* Wf     = (const float*)d_in[5];
    const float* bf     = (const float*)d_in[6];
    float* out = (float*)d_out;

    float *ifou, *cbuf, *hbuf, *iou, *fw;
    cudaGetSymbolAddress((void**)&ifou, g_ifou);
    cudaGetSymbolAddress((void**)&cbuf, g_c);
    cudaGetSymbolAddress((void**)&hbuf, g_h);
    cudaGetSymbolAddress((void**)&iou, g_iou);
    cudaGetSymbolAddress((void**)&fw, g_fw);

    cudaFuncSetAttribute(gemm_mma<0>, cudaFuncAttributeMaxDynamicSharedMemorySize, SMEM_BYTES);
    cudaFuncSetAttribute(gemm_mma<1>, cudaFuncAttributeMaxDynamicSharedMemorySize, SMEM_BYTES);

    init_kernel<<<1, 512>>>(cbuf, hbuf, fw);

    // ifou = inputs @ Wx + bx
    gemm_mma<0><<<dim3(2048 / 128, 4096 / 128), 256, SMEM_BYTES>>>(
        inputs, Wx, bx, ifou, nullptr, NN, 2048, 0);

    leaf_kernel<<<3072, 512>>>(ifou, bs, cbuf, hbuf);

    // fw for all leaves: h[0..3072) @ Wf + bf
    gemm_mma<0><<<dim3(512 / 128, 3072 / 128), 256, SMEM_BYTES>>>(
        hbuf, Wf, bf, fw, nullptr, 3072, 512, 0);

    static const int baseArr[6] = {3072, 3755, 4011, 4075, 4091, 4095};
    static const int cntArr[6]  = {683, 256, 64, 16, 4, 1};
    for (int l = 0; l < 6; ++l) {
        int m = cntArr[l], base = baseArr[l];
        gemm_mma<1><<<dim3(1536 / 128, (m + 127) / 128), 256, SMEM_BYTES>>>(
            nullptr, Ws, bs, iou, hbuf, m, 1536, base);
        combine_kernel<<<m, 512>>>(ifou, iou, fw, cbuf, hbuf, base);
        if (l < 5) {
            gemm_mma<0><<<dim3(512 / 128, (m + 127) / 128), 256, SMEM_BYTES>>>(
                hbuf + (size_t)base * 512, Wf, bf, fw + (size_t)base * 512,
                nullptr, m, 512, 0);
        }
    }

    copyout_kernel<<<1, 512>>>(hbuf, out);
}

// round 5
// speedup vs baseline: 1.6452x; 1.6452x over previous
#include <cuda_runtime.h>
#include <cuda_bf16.h>
#include <math.h>
#include <stdint.h>

#define NN 4096
#define MEM 512

// ---------------- scratch (static device globals; no allocation) ----------------
__device__ float g_ifou[NN * 2048];
__device__ float g_c[(NN + 1) * MEM];
__device__ float g_h[(NN + 1) * MEM];
__device__ float g_iou[683 * 1536];
__device__ float g_fw[(NN + 1) * MEM];

__device__ __forceinline__ float sigmoidf_(float x) { return 1.0f / (1.0f + expf(-x)); }

__device__ __forceinline__ int child_id(int p, int k) {
    int c = 4 * p - 12289 + k;
    return c < 0 ? NN : c;
}

// ---------------- bf16 split helpers ----------------
// pack two consecutive-k values into (hi_word, mid_word); low half = even k.
__device__ __forceinline__ uint2 split_pack(float x0, float x1) {
    __nv_bfloat162 h = __floats2bfloat162_rn(x0, x1);
    float r0 = x0 - __bfloat162float(h.x);
    float r1 = x1 - __bfloat162float(h.y);
    __nv_bfloat162 m = __floats2bfloat162_rn(r0, r1);
    uint2 o;
    o.x = *reinterpret_cast<uint32_t*>(&h);
    o.y = *reinterpret_cast<uint32_t*>(&m);
    return o;
}

__device__ __forceinline__ void mma16(float* d, const uint32_t* a, const uint32_t* b) {
    asm volatile(
        "mma.sync.aligned.m16n8k16.row.col.f32.bf16.bf16.f32 "
        "{%0,%1,%2,%3}, {%4,%5,%6,%7}, {%8,%9}, {%0,%1,%2,%3};"
        : "+f"(d[0]), "+f"(d[1]), "+f"(d[2]), "+f"(d[3])
        : "r"(a[0]), "r"(a[1]), "r"(a[2]), "r"(a[3]), "r"(b[0]), "r"(b[1]));
}

// ---------------- smem layout ----------------
// uint2 elements (hi,mid packed pair of 2 k-values).
// A: [2 buf][16 kp][128 row], B after A: same shape.
// XOR swizzle row^((kp&3)<<2): fragment LDS.64 conflict-free per half-warp phase.
constexpr int KC = 32;              // k per chunk
constexpr int KPC = KC / 2;         // 16 k-pairs per chunk
constexpr int NCH = 512 / KC;       // 16 chunks
__device__ __forceinline__ int a_off(int buf, int kp, int row) {
    return buf * (KPC * 128) + kp * 128 + (row ^ ((kp & 3) << 2));
}
__device__ __forceinline__ int b_off(int buf, int kp, int col) {
    return 2 * (KPC * 128) + buf * (KPC * 128) + kp * 128 + (col ^ ((kp & 3) << 2));
}
constexpr int SMEM_BYTES = 4 * KPC * 128 * 8;  // 64 KB

// ======================= bf16-split mma GEMM =======================
// C[M,Ncol] = A[M,512] @ B[512,Ncol] + bias (fp32-accurate via bf16 hi/mid split)
// MODE 0: dense A.  MODE 1: A row m = sum of 4 child h-rows of node pbase+m.
template <int MODE>
__global__ __launch_bounds__(256, 1)
void gemm_bf(const float* __restrict__ A, const float* __restrict__ B,
             const float* __restrict__ bias, float* __restrict__ C,
             const float* __restrict__ H, int M, int Ncol, int pbase) {
    extern __shared__ uint2 sm2[];
    const int tid = threadIdx.x;
    const int wid = tid >> 5;
    const int lid = tid & 31;
    const int bm = blockIdx.y * 128;
    const int bn = blockIdx.x * 128;
    const int wm = (wid & 1) * 64;
    const int wn = (wid >> 1) * 32;
    const int g = lid >> 2;
    const int c3 = lid & 3;

    // staging: thread t handles row/col = t&127, k-pair block (t>>7)*8 (8 kp = 16 k)
    const int srow = tid & 127;
    const int skpb = (tid >> 7) * 8;

    float va[16], vb[16];

    auto loadA = [&](int kb) {
        int gr = bm + srow;
        float4 v[4];
#pragma unroll
        for (int j = 0; j < 4; ++j) v[j] = make_float4(0.f, 0.f, 0.f, 0.f);
        if (gr < M) {
            if (MODE == 0) {
                const float* ap = A + (size_t)gr * 512 + kb + skpb * 2;
#pragma unroll
                for (int j = 0; j < 4; ++j)
                    v[j] = *reinterpret_cast<const float4*>(ap + 4 * j);
            } else {
                int p = pbase + gr;
#pragma unroll
                for (int kk = 0; kk < 4; ++kk) {
                    int cid = child_id(p, kk);
                    const float* hp = H + (size_t)cid * 512 + kb + skpb * 2;
#pragma unroll
                    for (int j = 0; j < 4; ++j) {
                        float4 t = *reinterpret_cast<const float4*>(hp + 4 * j);
                        v[j].x += t.x; v[j].y += t.y; v[j].z += t.z; v[j].w += t.w;
                    }
                }
            }
        }
#pragma unroll
        for (int j = 0; j < 4; ++j) {
            va[4 * j + 0] = v[j].x; va[4 * j + 1] = v[j].y;
            va[4 * j + 2] = v[j].z; va[4 * j + 3] = v[j].w;
        }
    };

    auto loadB = [&](int kb) {
        const float* bp = B + (size_t)(kb + skpb * 2) * Ncol + bn + srow;
#pragma unroll
        for (int j = 0; j < 16; ++j) vb[j] = bp[(size_t)j * Ncol];
    };

    auto storeAB = [&](int buf) {
#pragma unroll
        for (int i = 0; i < 8; ++i) {
            sm2[a_off(buf, skpb + i, srow)] = split_pack(va[2 * i], va[2 * i + 1]);
            sm2[b_off(buf, skpb + i, srow)] = split_pack(vb[2 * i], vb[2 * i + 1]);
        }
    };

    float acc[4][4][4];
#pragma unroll
    for (int mt = 0; mt < 4; ++mt)
#pragma unroll
        for (int nt = 0; nt < 4; ++nt)
#pragma unroll
            for (int i = 0; i < 4; ++i) acc[mt][nt][i] = 0.f;

    auto compute = [&](int buf) {
#pragma unroll
        for (int s = 0; s < 2; ++s) {   // two k16 blocks per chunk
            uint32_t ah[4][4], aml[4][4], bh[4][2], bml[4][2];
#pragma unroll
            for (int mt = 0; mt < 4; ++mt) {
                int r0 = wm + mt * 16 + g;
                uint2 t;
                t = sm2[a_off(buf, s * 8 + c3, r0)];      ah[mt][0] = t.x; aml[mt][0] = t.y;
                t = sm2[a_off(buf, s * 8 + c3, r0 + 8)];  ah[mt][1] = t.x; aml[mt][1] = t.y;
                t = sm2[a_off(buf, s * 8 + c3 + 4, r0)];      ah[mt][2] = t.x; aml[mt][2] = t.y;
                t = sm2[a_off(buf, s * 8 + c3 + 4, r0 + 8)];  ah[mt][3] = t.x; aml[mt][3] = t.y;
            }
#pragma unroll
            for (int nt = 0; nt < 4; ++nt) {
                int n0 = wn + nt * 8 + g;
                uint2 t;
                t = sm2[b_off(buf, s * 8 + c3, n0)];      bh[nt][0] = t.x; bml[nt][0] = t.y;
                t = sm2[b_off(buf, s * 8 + c3 + 4, n0)];  bh[nt][1] = t.x; bml[nt][1] = t.y;
            }
#pragma unroll
            for (int mt = 0; mt < 4; ++mt)
#pragma unroll
                for (int nt = 0; nt < 4; ++nt) {
                    mma16(acc[mt][nt], ah[mt], bh[nt]);
                    mma16(acc[mt][nt], ah[mt], bml[nt]);
                    mma16(acc[mt][nt], aml[mt], bh[nt]);
                }
        }
    };

    // pipeline
    loadA(0); loadB(0);
    storeAB(0);
    __syncthreads();
    for (int ch = 0; ch < NCH; ++ch) {
        if (ch + 1 < NCH) { loadA((ch + 1) * KC); loadB((ch + 1) * KC); }
        compute(ch & 1);
        __syncthreads();
        if (ch + 1 < NCH) {
            storeAB((ch + 1) & 1);
            __syncthreads();
        }
    }

    // epilogue
#pragma unroll
    for (int mt = 0; mt < 4; ++mt) {
        int r = bm + wm + mt * 16 + g;
        int r2 = r + 8;
#pragma unroll
        for (int nt = 0; nt < 4; ++nt) {
            int col = bn + wn + nt * 8 + 2 * c3;
            float b0 = bias[col], b1 = bias[col + 1];
            if (r < M) {
                float2 o = make_float2(acc[mt][nt][0] + b0, acc[mt][nt][1] + b1);
                *reinterpret_cast<float2*>(&C[(size_t)r * Ncol + col]) = o;
            }
            if (r2 < M) {
                float2 o = make_float2(acc[mt][nt][2] + b0, acc[mt][nt][3] + b1);
                *reinterpret_cast<float2*>(&C[(size_t)r2 * Ncol + col]) = o;
            }
        }
    }
}

// ---------------- elementwise kernels ----------------
__global__ void init_kernel(float* cbuf, float* hbuf, float* fw) {
    int j = threadIdx.x;
    cbuf[(size_t)NN * MEM + j] = 0.f;
    hbuf[(size_t)NN * MEM + j] = 0.f;
    fw[(size_t)NN * MEM + j] = 0.f;
}

__global__ void leaf_kernel(const float* __restrict__ ifou, const float* __restrict__ bs,
                            float* __restrict__ cbuf, float* __restrict__ hbuf) {
    int p = blockIdx.x;
    int j = threadIdx.x;
    const float* r = ifou + (size_t)p * 2048;
    float iv = sigmoidf_(r[j] + bs[j]);
    float ov = sigmoidf_(r[1024 + j] + bs[512 + j]);
    float uv = tanhf(r[1536 + j] + bs[1024 + j]);
    float c = iv * uv;
    cbuf[(size_t)p * MEM + j] = c;
    hbuf[(size_t)p * MEM + j] = ov * tanhf(c);
}

__global__ void combine_kernel(const float* __restrict__ ifou, const float* __restrict__ iou,
                               const float* __restrict__ fw, float* __restrict__ cbuf,
                               float* __restrict__ hbuf, int base) {
    int m = blockIdx.x;
    int j = threadIdx.x;
    int p = base + m;
    const float* r = ifou + (size_t)p * 2048;
    float ix = r[j], fx = r[512 + j], ox = r[1024 + j], ux = r[1536 + j];
    float iv = sigmoidf_(ix + iou[(size_t)m * 1536 + j]);
    float ov = sigmoidf_(ox + iou[(size_t)m * 1536 + 512 + j]);
    float uv = tanhf(ux + iou[(size_t)m * 1536 + 1024 + j]);
    float c = iv * uv;
#pragma unroll
    for (int k = 0; k < 4; ++k) {
        int cid = child_id(p, k);
        float f = sigmoidf_(fw[(size_t)cid * MEM + j] + fx);
        c += f * cbuf[(size_t)cid * MEM + j];
    }
    cbuf[(size_t)p * MEM + j] = c;
    hbuf[(size_t)p * MEM + j] = ov * tanhf(c);
}

__global__ void copyout_kernel(const float* __restrict__ hbuf, float* __restrict__ out) {
    out[threadIdx.x] = hbuf[(size_t)(NN - 1) * MEM + threadIdx.x];
}

// ---------------- launch ----------------
extern "C" void kernel_launch(void* const* d_in, const int* in_sizes, int n_in,
                              void* d_out, int out_size) {
    const float* inputs = (const float*)d_in[0];
    const float* Wx     = (const float*)d_in[1];
    const float* bx     = (const float*)d_in[2];
    const float* Ws     = (const float*)d_in[3];
    const float* bs     = (const float*)d_in[4];
    const float* Wf     = (const float*)d_in[5];
    const float* bf     = (const float*)d_in[6];
    float* out = (float*)d_out;

    float *ifou, *cbuf, *hbuf, *iou, *fw;
    cudaGetSymbolAddress((void**)&ifou, g_ifou);
    cudaGetSymbolAddress((void**)&cbuf, g_c);
    cudaGetSymbolAddress((void**)&hbuf, g_h);
    cudaGetSymbolAddress((void**)&iou, g_iou);
    cudaGetSymbolAddress((void**)&fw, g_fw);

    cudaFuncSetAttribute(gemm_bf<0>, cudaFuncAttributeMaxDynamicSharedMemorySize, SMEM_BYTES);
    cudaFuncSetAttribute(gemm_bf<1>, cudaFuncAttributeMaxDynamicSharedMemorySize, SMEM_BYTES);

    init_kernel<<<1, 512>>>(cbuf, hbuf, fw);

    // ifou = inputs @ Wx + bx
    gemm_bf<0><<<dim3(2048 / 128, 4096 / 128), 256, SMEM_BYTES>>>(
        inputs, Wx, bx, ifou, nullptr, NN, 2048, 0);

    leaf_kernel<<<3072, 512>>>(ifou, bs, cbuf, hbuf);

    // fw for all leaves: h[0..3072) @ Wf + bf
    gemm_bf<0><<<dim3(512 / 128, 3072 / 128), 256, SMEM_BYTES>>>(
        hbuf, Wf, bf, fw, nullptr, 3072, 512, 0);

    static const int baseArr[6] = {3072, 3755, 4011, 4075, 4091, 4095};
    static const int cntArr[6]  = {683, 256, 64, 16, 4, 1};
    for (int l = 0; l < 6; ++l) {
        int m = cntArr[l], base = baseArr[l];
        gemm_bf<1><<<dim3(1536 / 128, (m + 127) / 128), 256, SMEM_BYTES>>>(
            nullptr, Ws, bs, iou, hbuf, m, 1536, base);
        combine_kernel<<<m, 512>>>(ifou, iou, fw, cbuf, hbuf, base);
        if (l < 5) {
            gemm_bf<0><<<dim3(512 / 128, (m + 127) / 128), 256, SMEM_BYTES>>>(
                hbuf + (size_t)base * 512, Wf, bf, fw + (size_t)base * 512,
                nullptr, m, 512, 0);
        }
    }

    copyout_kernel<<<1, 512>>>(hbuf, out);
}

// round 7
// speedup vs baseline: 1.7408x; 1.0581x over previous
#include <cuda_runtime.h>
#include <cuda_bf16.h>
#include <math.h>
#include <stdint.h>

#define NN 4096
#define MEM 512
#define HS 4224   // padded row count for h_split (level tiles read past last node)

// ---------------- scratch (static device globals; no allocation) ----------------
__device__ float g_ifou[NN * 2048];
__device__ float g_c[(NN + 1) * MEM];
__device__ float g_h[(NN + 1) * MEM];
__device__ float g_iou[683 * 1536];
__device__ float g_fw[(NN + 1) * MEM];
// pre-split (hi,mid) bf16x2 pairs, packed per k-pair
__device__ uint2 g_wxs[256 * 2048];   // Wx split [kp][n]
__device__ uint2 g_wss[256 * 1536];   // Ws split [kp][n]
__device__ uint2 g_wfs[256 * 512];    // Wf split [kp][n]
__device__ uint2 g_isp[256 * 4096];   // inputs split, transposed [kp][row]
__device__ uint2 g_hsp[256 * HS];     // h split, transposed [kp][node]

__device__ __forceinline__ float sigmoidf_(float x) { return 1.0f / (1.0f + expf(-x)); }

__device__ __forceinline__ int child_id(int p, int k) {
    int c = 4 * p - 12289 + k;
    return c < 0 ? NN : c;
}

// ---------------- bf16 split helpers ----------------
__device__ __forceinline__ uint2 split_pack(float x0, float x1) {
    __nv_bfloat162 h = __floats2bfloat162_rn(x0, x1);
    float r0 = x0 - __bfloat162float(h.x);
    float r1 = x1 - __bfloat162float(h.y);
    __nv_bfloat162 m = __floats2bfloat162_rn(r0, r1);
    uint2 o;
    o.x = *reinterpret_cast<uint32_t*>(&h);
    o.y = *reinterpret_cast<uint32_t*>(&m);
    return o;
}

__device__ __forceinline__ void mma16(float* d, const uint32_t* a, const uint32_t* b) {
    asm volatile(
        "mma.sync.aligned.m16n8k16.row.col.f32.bf16.bf16.f32 "
        "{%0,%1,%2,%3}, {%4,%5,%6,%7}, {%8,%9}, {%0,%1,%2,%3};"
        : "+f"(d[0]), "+f"(d[1]), "+f"(d[2]), "+f"(d[3])
        : "r"(a[0]), "r"(a[1]), "r"(a[2]), "r"(a[3]), "r"(b[0]), "r"(b[1]));
}

__device__ __forceinline__ void cpa8(uint32_t dst, const void* src) {
    asm volatile("cp.async.ca.shared.global [%0], [%1], 8;" :: "r"(dst), "l"(src));
}
__device__ __forceinline__ void cpa16(uint32_t dst, const void* src) {
    asm volatile("cp.async.cg.shared.global [%0], [%1], 16;" :: "r"(dst), "l"(src));
}
__device__ __forceinline__ void cpa_commit() {
    asm volatile("cp.async.commit_group;" ::: "memory");
}
__device__ __forceinline__ void cpa_wait2() {
    asm volatile("cp.async.wait_group 2;" ::: "memory");
}

// ---------------- smem layout ----------------
constexpr int STAGES = 4;
constexpr int KC = 32;          // k per chunk
constexpr int KPC = KC / 2;     // 16 k-pairs
constexpr int NCH = 512 / KC;   // 16 chunks
__device__ __forceinline__ int a_off(int st, int kp, int row) {
    return st * (KPC * 128) + kp * 128 + (row ^ ((kp & 3) << 2));
}
__device__ __forceinline__ int b_off(int st, int kp, int col) {
    return STAGES * (KPC * 128) + st * (KPC * 128) + kp * 128 + (col ^ ((kp & 3) << 2));
}
constexpr int SMEM_BYTES = 2 * STAGES * KPC * 128 * 8;  // 128 KB

// ======================= async bf16-split GEMM =======================
// C[M,Ncol] = A[M,512] @ B[512,Ncol] + bias
// MODE 0: A from pre-split global Asp [kp][AS rows], row offset abase (cp.async)
// MODE 1: A row m = sum of 4 child h-rows (fp32 H) of node pbase+m (reg gather)
template <int MODE>
__global__ __launch_bounds__(256, 1)
void gemm_async(const uint2* __restrict__ Asp, int AS, int abase,
                const float* __restrict__ H, int pbase,
                const uint2* __restrict__ Bsp,
                const float* __restrict__ bias, float* __restrict__ C,
                int M, int Ncol) {
    extern __shared__ uint2 sm2[];
    const uint32_t sbase = (uint32_t)__cvta_generic_to_shared(sm2);
    const int tid = threadIdx.x;
    const int wid = tid >> 5;
    const int lid = tid & 31;
    const int bm = blockIdx.y * 128;
    const int bn = blockIdx.x * 128;
    const int wm = (wid & 1) * 64;
    const int wn = (wid >> 1) * 32;
    const int g = lid >> 2;
    const int c3 = lid & 3;

    // staging assignments
    const int srow = tid & 127;          // A row
    const int skpb = (tid >> 7) * 8;     // A: 8 kp per thread
    const int scol = (tid & 63) * 2;     // B: col pair
    const int skp4 = (tid >> 6) * 4;     // B: 4 kp per thread

    auto issueStage = [&](int ch, int st) {
        if (MODE == 0) {
#pragma unroll
            for (int i = 0; i < 8; ++i) {
                int kp = skpb + i;
                const uint2* src = Asp + (size_t)(ch * KPC + kp) * AS + abase + bm + srow;
                cpa8(sbase + (uint32_t)a_off(st, kp, srow) * 8, src);
            }
        } else {
            int gr = bm + srow;
            float v[16];
#pragma unroll
            for (int j = 0; j < 16; ++j) v[j] = 0.f;
            if (gr < M) {
                int p = pbase + gr;
                int kb = ch * KC + skpb * 2;
#pragma unroll
                for (int kk = 0; kk < 4; ++kk) {
                    int cid = child_id(p, kk);
                    const float* hp = H + (size_t)cid * 512 + kb;
#pragma unroll
                    for (int j = 0; j < 4; ++j) {
                        float4 t = *reinterpret_cast<const float4*>(hp + 4 * j);
                        v[4 * j + 0] += t.x; v[4 * j + 1] += t.y;
                        v[4 * j + 2] += t.z; v[4 * j + 3] += t.w;
                    }
                }
            }
#pragma unroll
            for (int i = 0; i < 8; ++i)
                sm2[a_off(st, skpb + i, srow)] = split_pack(v[2 * i], v[2 * i + 1]);
        }
#pragma unroll
        for (int i = 0; i < 4; ++i) {
            int kp = skp4 + i;
            const uint2* src = Bsp + (size_t)(ch * KPC + kp) * Ncol + bn + scol;
            cpa16(sbase + (uint32_t)b_off(st, kp, scol) * 8, src);
        }
    };

    float acc[4][4][4];
#pragma unroll
    for (int mt = 0; mt < 4; ++mt)
#pragma unroll
        for (int nt = 0; nt < 4; ++nt)
#pragma unroll
            for (int i = 0; i < 4; ++i) acc[mt][nt][i] = 0.f;

    auto compute = [&](int st) {
#pragma unroll
        for (int s = 0; s < 2; ++s) {
            uint32_t ah[4][4], aml[4][4], bh[4][2], bml[4][2];
#pragma unroll
            for (int mt = 0; mt < 4; ++mt) {
                int r0 = wm + mt * 16 + g;
                uint2 t;
                t = sm2[a_off(st, s * 8 + c3, r0)];          ah[mt][0] = t.x; aml[mt][0] = t.y;
                t = sm2[a_off(st, s * 8 + c3, r0 + 8)];      ah[mt][1] = t.x; aml[mt][1] = t.y;
                t = sm2[a_off(st, s * 8 + c3 + 4, r0)];      ah[mt][2] = t.x; aml[mt][2] = t.y;
                t = sm2[a_off(st, s * 8 + c3 + 4, r0 + 8)];  ah[mt][3] = t.x; aml[mt][3] = t.y;
            }
#pragma unroll
            for (int nt = 0; nt < 4; ++nt) {
                int n0 = wn + nt * 8 + g;
                uint2 t;
                t = sm2[b_off(st, s * 8 + c3, n0)];      bh[nt][0] = t.x; bml[nt][0] = t.y;
                t = sm2[b_off(st, s * 8 + c3 + 4, n0)];  bh[nt][1] = t.x; bml[nt][1] = t.y;
            }
#pragma unroll
            for (int mt = 0; mt < 4; ++mt)
#pragma unroll
                for (int nt = 0; nt < 4; ++nt) {
                    mma16(acc[mt][nt], ah[mt], bh[nt]);
                    mma16(acc[mt][nt], ah[mt], bml[nt]);
                    mma16(acc[mt][nt], aml[mt], bh[nt]);
                }
        }
    };

    // prologue: fill stages 0..STAGES-2
#pragma unroll
    for (int s = 0; s < STAGES - 1; ++s) {
        issueStage(s, s);
        cpa_commit();
    }
    for (int ch = 0; ch < NCH; ++ch) {
        cpa_wait2();
        __syncthreads();
        int nx = ch + STAGES - 1;
        if (nx < NCH) issueStage(nx, nx & (STAGES - 1));
        cpa_commit();
        compute(ch & (STAGES - 1));
    }

    // epilogue
#pragma unroll
    for (int mt = 0; mt < 4; ++mt) {
        int r = bm + wm + mt * 16 + g;
        int r2 = r + 8;
#pragma unroll
        for (int nt = 0; nt < 4; ++nt) {
            int col = bn + wn + nt * 8 + 2 * c3;
            float b0 = bias[col], b1 = bias[col + 1];
            if (r < M) {
                float2 o = make_float2(acc[mt][nt][0] + b0, acc[mt][nt][1] + b1);
                *reinterpret_cast<float2*>(&C[(size_t)r * Ncol + col]) = o;
            }
            if (r2 < M) {
                float2 o = make_float2(acc[mt][nt][2] + b0, acc[mt][nt][3] + b1);
                *reinterpret_cast<float2*>(&C[(size_t)r2 * Ncol + col]) = o;
            }
        }
    }
}

// ---------------- pre-split kernels ----------------
// weights: W[512][Ncol] -> out[kp][Ncol]
__global__ void split_w_kernel(const float* __restrict__ W, uint2* __restrict__ out, int Ncol) {
    int n = blockIdx.x * 256 + threadIdx.x;
    int kp = blockIdx.y;
    float a = W[(size_t)(2 * kp) * Ncol + n];
    float b = W[(size_t)(2 * kp + 1) * Ncol + n];
    out[(size_t)kp * Ncol + n] = split_pack(a, b);
}

// inputs[4096][512] -> isp[kp][4096] (smem transpose)
__global__ void split_in_kernel(const float* __restrict__ in, uint2* __restrict__ out) {
    __shared__ float2 tile[32][33];
    int row = blockIdx.x * 32 + threadIdx.y;
    int kp = blockIdx.y * 32 + threadIdx.x;
    tile[threadIdx.y][threadIdx.x] = *reinterpret_cast<const float2*>(in + (size_t)row * 512 + 2 * kp);
    __syncthreads();
    int orow = blockIdx.x * 32 + threadIdx.x;
    int okp = blockIdx.y * 32 + threadIdx.y;
    float2 v = tile[threadIdx.x][threadIdx.y];
    out[(size_t)okp * 4096 + orow] = split_pack(v.x, v.y);
}

// ---------------- elementwise kernels ----------------
__global__ void init_kernel(float* cbuf, float* hbuf) {
    int j = threadIdx.x;
    cbuf[(size_t)NN * MEM + j] = 0.f;
    hbuf[(size_t)NN * MEM + j] = 0.f;
}

__global__ void leaf_kernel(const float* __restrict__ ifou, const float* __restrict__ bs,
                            float* __restrict__ cbuf, float* __restrict__ hbuf,
                            uint2* __restrict__ hsp) {
    int p = blockIdx.x;
    int j = threadIdx.x;
    const float* r = ifou + (size_t)p * 2048;
    float iv = sigmoidf_(r[j] + bs[j]);
    float ov = sigmoidf_(r[1024 + j] + bs[512 + j]);
    float uv = tanhf(r[1536 + j] + bs[1024 + j]);
    float c = iv * uv;
    float h = ov * tanhf(c);
    cbuf[(size_t)p * MEM + j] = c;
    hbuf[(size_t)p * MEM + j] = h;
    float hn = __shfl_down_sync(0xffffffffu, h, 1);
    if ((j & 1) == 0) hsp[(size_t)(j >> 1) * HS + p] = split_pack(h, hn);
}

__global__ void combine_kernel(const float* __restrict__ ifou, const float* __restrict__ iou,
                               const float* __restrict__ fw, float* __restrict__ cbuf,
                               float* __restrict__ hbuf, uint2* __restrict__ hsp, int base) {
    int m = blockIdx.x;
    int j = threadIdx.x;
    int p = base + m;
    const float* r = ifou + (size_t)p * 2048;
    float ix = r[j], fx = r[512 + j], ox = r[1024 + j], ux = r[1536 + j];
    float iv = sigmoidf_(ix + iou[(size_t)m * 1536 + j]);
    float ov = sigmoidf_(ox + iou[(size_t)m * 1536 + 512 + j]);
    float uv = tanhf(ux + iou[(size_t)m * 1536 + 1024 + j]);
    float c = iv * uv;
#pragma unroll
    for (int k = 0; k < 4; ++k) {
        int cid = child_id(p, k);
        float f = sigmoidf_(fw[(size_t)cid * MEM + j] + fx);
        c += f * cbuf[(size_t)cid * MEM + j];
    }
    float h = ov * tanhf(c);
    cbuf[(size_t)p * MEM + j] = c;
    hbuf[(size_t)p * MEM + j] = h;
    float hn = __shfl_down_sync(0xffffffffu, h, 1);
    if ((j & 1) == 0) hsp[(size_t)(j >> 1) * HS + p] = split_pack(h, hn);
}

__global__ void copyout_kernel(const float* __restrict__ hbuf, float* __restrict__ out) {
    out[threadIdx.x] = hbuf[(size_t)(NN - 1) * MEM + threadIdx.x];
}

// ---------------- launch ----------------
extern "C" void kernel_launch(void* const* d_in, const int* in_sizes, int n_in,
                              void* d_out, int out_size) {
    const float* inputs = (const float*)d_in[0];
    const float* Wx     = (const float*)d_in[1];
    const float* bx     = (const float*)d_in[2];
    const float* Ws     = (const float*)d_in[3];
    const float* bs     = (const float*)d_in[4];
    const float* Wf     = (const float*)d_in[5];
    const float* bf     = (const float*)d_in[6];
    float* out = (float*)d_out;

    float *ifou, *cbuf, *hbuf, *iou, *fw;
    uint2 *wxs, *wss, *wfs, *isp, *hsp;
    cudaGetSymbolAddress((void**)&ifou, g_ifou);
    cudaGetSymbolAddress((void**)&cbuf, g_c);
    cudaGetSymbolAddress((void**)&hbuf, g_h);
    cudaGetSymbolAddress((void**)&iou, g_iou);
    cudaGetSymbolAddress((void**)&fw, g_fw);
    cudaGetSymbolAddress((void**)&wxs, g_wxs);
    cudaGetSymbolAddress((void**)&wss, g_wss);
    cudaGetSymbolAddress((void**)&wfs, g_wfs);
    cudaGetSymbolAddress((void**)&isp, g_isp);
    cudaGetSymbolAddress((void**)&hsp, g_hsp);

    cudaFuncSetAttribute(gemm_async<0>, cudaFuncAttributeMaxDynamicSharedMemorySize, SMEM_BYTES);
    cudaFuncSetAttribute(gemm_async<1>, cudaFuncAttributeMaxDynamicSharedMemorySize, SMEM_BYTES);

    init_kernel<<<1, 512>>>(cbuf, hbuf);

    // pre-split constants
    split_w_kernel<<<dim3(2048 / 256, 256), 256>>>(Wx, wxs, 2048);
    split_w_kernel<<<dim3(1536 / 256, 256), 256>>>(Ws, wss, 1536);
    split_w_kernel<<<dim3(512 / 256, 256), 256>>>(Wf, wfs, 512);
    split_in_kernel<<<dim3(4096 / 32, 256 / 32), dim3(32, 32)>>>(inputs, isp);

    // ifou = inputs @ Wx + bx
    gemm_async<0><<<dim3(2048 / 128, 4096 / 128), 256, SMEM_BYTES>>>(
        isp, 4096, 0, nullptr, 0, wxs, bx, ifou, NN, 2048);

    leaf_kernel<<<3072, 512>>>(ifou, bs, cbuf, hbuf, hsp);

    // fw for all leaves: h[0..3072) @ Wf + bf
    gemm_async<0><<<dim3(512 / 128, 3072 / 128), 256, SMEM_BYTES>>>(
        hsp, HS, 0, nullptr, 0, wfs, bf, fw, 3072, 512);

    static const int baseArr[6] = {3072, 3755, 4011, 4075, 4091, 4095};
    static const int cntArr[6]  = {683, 256, 64, 16, 4, 1};
    for (int l = 0; l < 6; ++l) {
        int m = cntArr[l], base = baseArr[l];
        gemm_async<1><<<dim3(1536 / 128, (m + 127) / 128), 256, SMEM_BYTES>>>(
            nullptr, 0, 0, hbuf, base, wss, bs, iou, m, 1536);
        combine_kernel<<<m, 512>>>(ifou, iou, fw, cbuf, hbuf, hsp, base);
        if (l < 5) {
            gemm_async<0><<<dim3(512 / 128, (m + 127) / 128), 256, SMEM_BYTES>>>(
                hsp, HS, base, nullptr, 0, wfs, bf, fw + (size_t)base * 512, m, 512);
        }
    }

    copyout_kernel<<<1, 512>>>(hbuf, out);
}

// round 8
// speedup vs baseline: 2.3615x; 1.3566x over previous
#include <cuda_runtime.h>
#include <cuda_bf16.h>
#include <math.h>
#include <stdint.h>

#define NN 4096
#define MEM 512
#define HS 4224   // padded row count for h_split (level tiles read past last node)

// ---------------- scratch (static device globals; no allocation) ----------------
__device__ float g_ifou[NN * 2048];
__device__ float g_c[(NN + 1) * MEM];
__device__ float g_h[(NN + 1) * MEM];
__device__ float g_iou[683 * 1536];
__device__ float g_fw[(NN + 1) * MEM];
// pre-split (hi,mid) bf16x2 pairs, packed per k-pair
__device__ uint2 g_wxs[256 * 2048];   // Wx split [kp][n]
__device__ uint2 g_wss[256 * 1536];   // Ws split [kp][n]
__device__ uint2 g_wfs[256 * 512];    // Wf split [kp][n]
__device__ uint2 g_isp[256 * 4096];   // inputs split, transposed [kp][row]
__device__ uint2 g_hsp[256 * HS];     // h split, transposed [kp][node]

__device__ __forceinline__ float sigmoidf_(float x) { return 1.0f / (1.0f + expf(-x)); }

__device__ __forceinline__ int child_id(int p, int k) {
    int c = 4 * p - 12289 + k;
    return c < 0 ? NN : c;
}

// ---------------- bf16 split helpers ----------------
__device__ __forceinline__ uint2 split_pack(float x0, float x1) {
    __nv_bfloat162 h = __floats2bfloat162_rn(x0, x1);
    float r0 = x0 - __bfloat162float(h.x);
    float r1 = x1 - __bfloat162float(h.y);
    __nv_bfloat162 m = __floats2bfloat162_rn(r0, r1);
    uint2 o;
    o.x = *reinterpret_cast<uint32_t*>(&h);
    o.y = *reinterpret_cast<uint32_t*>(&m);
    return o;
}

__device__ __forceinline__ void mma16(float* d, const uint32_t* a, const uint32_t* b) {
    asm volatile(
        "mma.sync.aligned.m16n8k16.row.col.f32.bf16.bf16.f32 "
        "{%0,%1,%2,%3}, {%4,%5,%6,%7}, {%8,%9}, {%0,%1,%2,%3};"
        : "+f"(d[0]), "+f"(d[1]), "+f"(d[2]), "+f"(d[3])
        : "r"(a[0]), "r"(a[1]), "r"(a[2]), "r"(a[3]), "r"(b[0]), "r"(b[1]));
}

__device__ __forceinline__ void cpa8(uint32_t dst, const void* src) {
    asm volatile("cp.async.ca.shared.global [%0], [%1], 8;" :: "r"(dst), "l"(src));
}
__device__ __forceinline__ void cpa16(uint32_t dst, const void* src) {
    asm volatile("cp.async.cg.shared.global [%0], [%1], 16;" :: "r"(dst), "l"(src));
}
__device__ __forceinline__ void cpa_commit() {
    asm volatile("cp.async.commit_group;" ::: "memory");
}
__device__ __forceinline__ void cpa_wait2() {
    asm volatile("cp.async.wait_group 2;" ::: "memory");
}

// ---------------- smem layout ----------------
constexpr int STAGES = 4;
constexpr int KC = 32;          // k per chunk
constexpr int KPC = KC / 2;     // 16 k-pairs
constexpr int NCH = 512 / KC;   // 16 chunks
__device__ __forceinline__ int a_off(int st, int kp, int row) {
    return st * (KPC * 128) + kp * 128 + (row ^ ((kp & 3) << 2));
}
__device__ __forceinline__ int b_off(int st, int kp, int col) {
    return STAGES * (KPC * 128) + st * (KPC * 128) + kp * 128 + (col ^ ((kp & 3) << 2));
}
constexpr int SMEM_BYTES = 2 * STAGES * KPC * 128 * 8;  // 128 KB

// ======================= async bf16-split GEMM body =======================
// C[bm:bm+128, bn:bn+128] for C = A[M,512] @ B[512,Ncol] + bias
// MODE 0: A from pre-split global Asp [kp][AS rows], row offset abase (cp.async)
// MODE 1: A row m = sum of 4 child h-rows (fp32 H) of node pbase+m (reg gather)
template <int MODE>
__device__ __forceinline__
void gemm_body(const uint2* __restrict__ Asp, int AS, int abase,
               const float* __restrict__ H, int pbase,
               const uint2* __restrict__ Bsp,
               const float* __restrict__ bias, float* __restrict__ C,
               int M, int Ncol, int bm, int bn) {
    extern __shared__ uint2 sm2[];
    const uint32_t sbase = (uint32_t)__cvta_generic_to_shared(sm2);
    const int tid = threadIdx.x;
    const int wid = tid >> 5;
    const int lid = tid & 31;
    const int wm = (wid & 1) * 64;
    const int wn = (wid >> 1) * 32;
    const int g = lid >> 2;
    const int c3 = lid & 3;

    // staging assignments
    const int srow = tid & 127;          // A row
    const int skpb = (tid >> 7) * 8;     // A: 8 kp per thread
    const int scol = (tid & 63) * 2;     // B: col pair
    const int skp4 = (tid >> 6) * 4;     // B: 4 kp per thread

    auto issueStage = [&](int ch, int st) {
        if (MODE == 0) {
#pragma unroll
            for (int i = 0; i < 8; ++i) {
                int kp = skpb + i;
                const uint2* src = Asp + (size_t)(ch * KPC + kp) * AS + abase + bm + srow;
                cpa8(sbase + (uint32_t)a_off(st, kp, srow) * 8, src);
            }
        } else {
            int gr = bm + srow;
            float v[16];
#pragma unroll
            for (int j = 0; j < 16; ++j) v[j] = 0.f;
            if (gr < M) {
                int p = pbase + gr;
                int kb = ch * KC + skpb * 2;
#pragma unroll
                for (int kk = 0; kk < 4; ++kk) {
                    int cid = child_id(p, kk);
                    const float* hp = H + (size_t)cid * 512 + kb;
#pragma unroll
                    for (int j = 0; j < 4; ++j) {
                        float4 t = *reinterpret_cast<const float4*>(hp + 4 * j);
                        v[4 * j + 0] += t.x; v[4 * j + 1] += t.y;
                        v[4 * j + 2] += t.z; v[4 * j + 3] += t.w;
                    }
                }
            }
#pragma unroll
            for (int i = 0; i < 8; ++i)
                sm2[a_off(st, skpb + i, srow)] = split_pack(v[2 * i], v[2 * i + 1]);
        }
#pragma unroll
        for (int i = 0; i < 4; ++i) {
            int kp = skp4 + i;
            const uint2* src = Bsp + (size_t)(ch * KPC + kp) * Ncol + bn + scol;
            cpa16(sbase + (uint32_t)b_off(st, kp, scol) * 8, src);
        }
    };

    float acc[4][4][4];
#pragma unroll
    for (int mt = 0; mt < 4; ++mt)
#pragma unroll
        for (int nt = 0; nt < 4; ++nt)
#pragma unroll
            for (int i = 0; i < 4; ++i) acc[mt][nt][i] = 0.f;

    auto compute = [&](int st) {
#pragma unroll
        for (int s = 0; s < 2; ++s) {
            uint32_t ah[4][4], aml[4][4], bh[4][2], bml[4][2];
#pragma unroll
            for (int mt = 0; mt < 4; ++mt) {
                int r0 = wm + mt * 16 + g;
                uint2 t;
                t = sm2[a_off(st, s * 8 + c3, r0)];          ah[mt][0] = t.x; aml[mt][0] = t.y;
                t = sm2[a_off(st, s * 8 + c3, r0 + 8)];      ah[mt][1] = t.x; aml[mt][1] = t.y;
                t = sm2[a_off(st, s * 8 + c3 + 4, r0)];      ah[mt][2] = t.x; aml[mt][2] = t.y;
                t = sm2[a_off(st, s * 8 + c3 + 4, r0 + 8)];  ah[mt][3] = t.x; aml[mt][3] = t.y;
            }
#pragma unroll
            for (int nt = 0; nt < 4; ++nt) {
                int n0 = wn + nt * 8 + g;
                uint2 t;
                t = sm2[b_off(st, s * 8 + c3, n0)];      bh[nt][0] = t.x; bml[nt][0] = t.y;
                t = sm2[b_off(st, s * 8 + c3 + 4, n0)];  bh[nt][1] = t.x; bml[nt][1] = t.y;
            }
            // term-major ordering: 16 independent MMAs between accumulator reuses
#pragma unroll
            for (int mt = 0; mt < 4; ++mt)
#pragma unroll
                for (int nt = 0; nt < 4; ++nt)
                    mma16(acc[mt][nt], ah[mt], bh[nt]);
#pragma unroll
            for (int mt = 0; mt < 4; ++mt)
#pragma unroll
                for (int nt = 0; nt < 4; ++nt)
                    mma16(acc[mt][nt], ah[mt], bml[nt]);
#pragma unroll
            for (int mt = 0; mt < 4; ++mt)
#pragma unroll
                for (int nt = 0; nt < 4; ++nt)
                    mma16(acc[mt][nt], aml[mt], bh[nt]);
        }
    };

    // prologue: fill stages 0..STAGES-2
#pragma unroll
    for (int s = 0; s < STAGES - 1; ++s) {
        issueStage(s, s);
        cpa_commit();
    }
    for (int ch = 0; ch < NCH; ++ch) {
        cpa_wait2();
        __syncthreads();
        int nx = ch + STAGES - 1;
        if (nx < NCH) issueStage(nx, nx & (STAGES - 1));
        cpa_commit();
        compute(ch & (STAGES - 1));
    }

    // epilogue
#pragma unroll
    for (int mt = 0; mt < 4; ++mt) {
        int r = bm + wm + mt * 16 + g;
        int r2 = r + 8;
#pragma unroll
        for (int nt = 0; nt < 4; ++nt) {
            int col = bn + wn + nt * 8 + 2 * c3;
            float b0 = bias[col], b1 = bias[col + 1];
            if (r < M) {
                float2 o = make_float2(acc[mt][nt][0] + b0, acc[mt][nt][1] + b1);
                *reinterpret_cast<float2*>(&C[(size_t)r * Ncol + col]) = o;
            }
            if (r2 < M) {
                float2 o = make_float2(acc[mt][nt][2] + b0, acc[mt][nt][3] + b1);
                *reinterpret_cast<float2*>(&C[(size_t)r2 * Ncol + col]) = o;
            }
        }
    }
}

// plain single-GEMM kernel (used for ifou)
template <int MODE>
__global__ __launch_bounds__(256, 1)
void gemm_async(const uint2* __restrict__ Asp, int AS, int abase,
                const float* __restrict__ H, int pbase,
                const uint2* __restrict__ Bsp,
                const float* __restrict__ bias, float* __restrict__ C,
                int M, int Ncol) {
    gemm_body<MODE>(Asp, AS, abase, H, pbase, Bsp, bias, C, M, Ncol,
                    blockIdx.y * 128, blockIdx.x * 128);
}

// dual kernel: z=0 -> iou GEMM (MODE1 gather), z=1 -> fw GEMM (MODE0 dense)
__global__ __launch_bounds__(256, 1)
void gemm_dual(const float* __restrict__ H, int pbase,
               const uint2* __restrict__ wss, const float* __restrict__ bs,
               float* __restrict__ iou, int M1,
               const uint2* __restrict__ hsp, int abase,
               const uint2* __restrict__ wfs, const float* __restrict__ bf,
               float* __restrict__ fwout, int M0) {
    if (blockIdx.z == 0) {
        if ((int)blockIdx.x >= 12 || (int)(blockIdx.y * 128) >= M1) return;
        gemm_body<1>(nullptr, 0, 0, H, pbase, wss, bs, iou, M1, 1536,
                     blockIdx.y * 128, blockIdx.x * 128);
    } else {
        if ((int)blockIdx.x >= 4 || (int)(blockIdx.y * 128) >= M0) return;
        gemm_body<0>(hsp, HS, abase, nullptr, 0, wfs, bf, fwout, M0, 512,
                     blockIdx.y * 128, blockIdx.x * 128);
    }
}

// ---------------- pre-split kernels ----------------
// all three weight matrices in one launch, flattened over 4096 columns
__global__ void split_w_all(const float* __restrict__ Wx, const float* __restrict__ Ws,
                            const float* __restrict__ Wf,
                            uint2* __restrict__ wxs, uint2* __restrict__ wss,
                            uint2* __restrict__ wfs) {
    int n = blockIdx.x * 256 + threadIdx.x;   // 0..4095
    int kp = blockIdx.y;                      // 0..255
    const float* W; uint2* out; int Ncol; int nn;
    if (n < 2048)      { W = Wx; out = wxs; Ncol = 2048; nn = n; }
    else if (n < 3584) { W = Ws; out = wss; Ncol = 1536; nn = n - 2048; }
    else               { W = Wf; out = wfs; Ncol = 512;  nn = n - 3584; }
    float a = W[(size_t)(2 * kp) * Ncol + nn];
    float b = W[(size_t)(2 * kp + 1) * Ncol + nn];
    out[(size_t)kp * Ncol + nn] = split_pack(a, b);
}

// inputs[4096][512] -> isp[kp][4096] (smem transpose)
__global__ void split_in_kernel(const float* __restrict__ in, uint2* __restrict__ out) {
    __shared__ float2 tile[32][33];
    int row = blockIdx.x * 32 + threadIdx.y;
    int kp = blockIdx.y * 32 + threadIdx.x;
    tile[threadIdx.y][threadIdx.x] = *reinterpret_cast<const float2*>(in + (size_t)row * 512 + 2 * kp);
    __syncthreads();
    int orow = blockIdx.x * 32 + threadIdx.x;
    int okp = blockIdx.y * 32 + threadIdx.y;
    float2 v = tile[threadIdx.x][threadIdx.y];
    out[(size_t)okp * 4096 + orow] = split_pack(v.x, v.y);
}

// ---------------- elementwise kernels ----------------
__global__ void init_kernel(float* cbuf, float* hbuf) {
    int j = threadIdx.x;
    cbuf[(size_t)NN * MEM + j] = 0.f;
    hbuf[(size_t)NN * MEM + j] = 0.f;
}

__global__ void leaf_kernel(const float* __restrict__ ifou, const float* __restrict__ bs,
                            float* __restrict__ cbuf, float* __restrict__ hbuf,
                            uint2* __restrict__ hsp) {
    int p = blockIdx.x;
    int j = threadIdx.x;
    const float* r = ifou + (size_t)p * 2048;
    float iv = sigmoidf_(r[j] + bs[j]);
    float ov = sigmoidf_(r[1024 + j] + bs[512 + j]);
    float uv = tanhf(r[1536 + j] + bs[1024 + j]);
    float c = iv * uv;
    float h = ov * tanhf(c);
    cbuf[(size_t)p * MEM + j] = c;
    hbuf[(size_t)p * MEM + j] = h;
    float hn = __shfl_down_sync(0xffffffffu, h, 1);
    if ((j & 1) == 0) hsp[(size_t)(j >> 1) * HS + p] = split_pack(h, hn);
}

__global__ void combine_kernel(const float* __restrict__ ifou, const float* __restrict__ iou,
                               const float* __restrict__ fw, float* __restrict__ cbuf,
                               float* __restrict__ hbuf, uint2* __restrict__ hsp, int base) {
    int m = blockIdx.x;
    int j = threadIdx.x;
    int p = base + m;
    const float* r = ifou + (size_t)p * 2048;
    float ix = r[j], fx = r[512 + j], ox = r[1024 + j], ux = r[1536 + j];
    float iv = sigmoidf_(ix + iou[(size_t)m * 1536 + j]);
    float ov = sigmoidf_(ox + iou[(size_t)m * 1536 + 512 + j]);
    float uv = tanhf(ux + iou[(size_t)m * 1536 + 1024 + j]);
    float c = iv * uv;
#pragma unroll
    for (int k = 0; k < 4; ++k) {
        int cid = child_id(p, k);
        float f = sigmoidf_(fw[(size_t)cid * MEM + j] + fx);
        c += f * cbuf[(size_t)cid * MEM + j];
    }
    float h = ov * tanhf(c);
    cbuf[(size_t)p * MEM + j] = c;
    hbuf[(size_t)p * MEM + j] = h;
    float hn = __shfl_down_sync(0xffffffffu, h, 1);
    if ((j & 1) == 0) hsp[(size_t)(j >> 1) * HS + p] = split_pack(h, hn);
}

__global__ void copyout_kernel(const float* __restrict__ hbuf, float* __restrict__ out) {
    out[threadIdx.x] = hbuf[(size_t)(NN - 1) * MEM + threadIdx.x];
}

// ---------------- launch ----------------
extern "C" void kernel_launch(void* const* d_in, const int* in_sizes, int n_in,
                              void* d_out, int out_size) {
    const float* inputs = (const float*)d_in[0];
    const float* Wx     = (const float*)d_in[1];
    const float* bx     = (const float*)d_in[2];
    const float* Ws     = (const float*)d_in[3];
    const float* bs     = (const float*)d_in[4];
    const float* Wf     = (const float*)d_in[5];
    const float* bf     = (const float*)d_in[6];
    float* out = (float*)d_out;

    float *ifou, *cbuf, *hbuf, *iou, *fw;
    uint2 *wxs, *wss, *wfs, *isp, *hsp;
    cudaGetSymbolAddress((void**)&ifou, g_ifou);
    cudaGetSymbolAddress((void**)&cbuf, g_c);
    cudaGetSymbolAddress((void**)&hbuf, g_h);
    cudaGetSymbolAddress((void**)&iou, g_iou);
    cudaGetSymbolAddress((void**)&fw, g_fw);
    cudaGetSymbolAddress((void**)&wxs, g_wxs);
    cudaGetSymbolAddress((void**)&wss, g_wss);
    cudaGetSymbolAddress((void**)&wfs, g_wfs);
    cudaGetSymbolAddress((void**)&isp, g_isp);
    cudaGetSymbolAddress((void**)&hsp, g_hsp);

    cudaFuncSetAttribute(gemm_async<0>, cudaFuncAttributeMaxDynamicSharedMemorySize, SMEM_BYTES);
    cudaFuncSetAttribute(gemm_dual, cudaFuncAttributeMaxDynamicSharedMemorySize, SMEM_BYTES);

    init_kernel<<<1, 512>>>(cbuf, hbuf);

    // pre-split constants
    split_w_all<<<dim3(16, 256), 256>>>(Wx, Ws, Wf, wxs, wss, wfs);
    split_in_kernel<<<dim3(4096 / 32, 256 / 32), dim3(32, 32)>>>(inputs, isp);

    // ifou = inputs @ Wx + bx
    gemm_async<0><<<dim3(2048 / 128, 4096 / 128), 256, SMEM_BYTES>>>(
        isp, 4096, 0, nullptr, 0, wxs, bx, ifou, NN, 2048);

    leaf_kernel<<<3072, 512>>>(ifou, bs, cbuf, hbuf, hsp);

    static const int baseArr[6] = {3072, 3755, 4011, 4075, 4091, 4095};
    static const int cntArr[6]  = {683, 256, 64, 16, 4, 1};
    int prevBase = 0, prevCnt = 3072;
    for (int l = 0; l < 6; ++l) {
        int m = cntArr[l], base = baseArr[l];
        int gy = (m + 127) / 128;
        int gy0 = (prevCnt + 127) / 128;
        int gymax = gy > gy0 ? gy : gy0;
        // z=0: iou_l = (sum child h) @ Ws + bs ; z=1: fw of previous level
        gemm_dual<<<dim3(12, gymax, 2), 256, SMEM_BYTES>>>(
            hbuf, base, wss, bs, iou, m,
            hsp, prevBase, wfs, bf, fw + (size_t)prevBase * 512, prevCnt);
        combine_kernel<<<m, 512>>>(ifou, iou, fw, cbuf, hbuf, hsp, base);
        prevBase = base;
        prevCnt = m;
    }

    copyout_kernel<<<1, 512>>>(hbuf, out);
}